// round 1
// baseline (speedup 1.0000x reference)
#include <cuda_runtime.h>

#define NN   50000
#define NE   500000
#define D    128
#define NREL 51
#define NL   4
#define QB   1024
#define QK   32
#define KTOT 1664     // 13 * D
#define TM   128
#define TKC  32

// ---------------- static device scratch (no allocations allowed) ----------------
__device__ int   g_deg[NN];
__device__ int   g_rowstart[NN + 1];
__device__ int   g_cursor[NN];
__device__ int   g_perm[NE];
__device__ float g_scales[NN * 4];     // {1, scale, 1/clip(scale), 1}
__device__ float g_logsum;
__device__ float g_mean[NN * D];
__device__ float g_fmax[NN * D];
__device__ float g_fmin[NN * D];
__device__ float g_fstd[NN * D];
__device__ float g_xa[NN * D];
__device__ float g_xb[NN * D];

// ---------------- f32x2 helpers ----------------
__device__ __forceinline__ unsigned long long pk2(float x, float y) {
    unsigned long long r;
    asm("mov.b64 %0, {%1,%2};" : "=l"(r) : "f"(x), "f"(y));
    return r;
}
__device__ __forceinline__ void fma2(unsigned long long& c, unsigned long long a, unsigned long long b) {
    asm("fma.rn.f32x2 %0, %1, %2, %0;" : "+l"(c) : "l"(a), "l"(b));
}
__device__ __forceinline__ float2 up2(unsigned long long v) {
    float x, y;
    asm("mov.b64 {%0,%1}, %2;" : "=f"(x), "=f"(y) : "l"(v));
    return make_float2(x, y);
}

// ---------------- CSR build ----------------
__global__ void k_init() {
    int i = blockIdx.x * blockDim.x + threadIdx.x;
    if (i < NN) g_deg[i] = 0;
    if (i == 0) g_logsum = 0.f;
}

__global__ void k_hist(const int* __restrict__ edst) {
    int e = blockIdx.x * blockDim.x + threadIdx.x;
    if (e < NE) atomicAdd(&g_deg[edst[e]], 1);
}

__global__ void k_scan() {   // single block, 1024 threads
    __shared__ int sh[1024];
    __shared__ int carry;
    int tid = threadIdx.x;
    if (tid == 0) { carry = 0; g_rowstart[0] = 0; }
    __syncthreads();
    for (int base = 0; base < NN; base += 1024) {
        int idx = base + tid;
        int v = (idx < NN) ? g_deg[idx] : 0;
        sh[tid] = v;
        __syncthreads();
        for (int off = 1; off < 1024; off <<= 1) {
            int t = (tid >= off) ? sh[tid - off] : 0;
            __syncthreads();
            sh[tid] += t;
            __syncthreads();
        }
        int inc = sh[tid] + carry;
        if (idx < NN) { g_rowstart[idx + 1] = inc; g_cursor[idx] = inc - v; }
        __syncthreads();
        if (tid == 0) carry = carry + sh[1023];
        __syncthreads();
    }
}

__global__ void k_scatter(const int* __restrict__ edst) {
    int e = blockIdx.x * blockDim.x + threadIdx.x;
    if (e < NE) {
        int p = atomicAdd(&g_cursor[edst[e]], 1);
        g_perm[p] = e;
    }
}

// ---------------- PNA degree scalers ----------------
__global__ void k_logsum() {
    int i = blockIdx.x * blockDim.x + threadIdx.x;
    float v = 0.f;
    if (i < NN) v = logf((float)g_deg[i] + 1.0f);
    #pragma unroll
    for (int o = 16; o > 0; o >>= 1) v += __shfl_xor_sync(0xffffffffu, v, o);
    if ((threadIdx.x & 31) == 0 && v != 0.f) atomicAdd(&g_logsum, v);
}

__global__ void k_scales() {
    int i = blockIdx.x * blockDim.x + threadIdx.x;
    if (i >= NN) return;
    float mean = g_logsum * (1.0f / (float)NN);
    float s = logf((float)g_deg[i] + 1.0f) / mean;
    g_scales[i * 4 + 0] = 1.0f;
    g_scales[i * 4 + 1] = s;
    g_scales[i * 4 + 2] = 1.0f / fmaxf(s, 1e-2f);
    g_scales[i * 4 + 3] = 1.0f;   // used by raw-x block of the linear
}

__global__ void k_copy(const float* __restrict__ x0) {
    int i = blockIdx.x * blockDim.x + threadIdx.x;
    if (i < NN * D / 4) ((float4*)g_xa)[i] = ((const float4*)x0)[i];
}

// ---------------- per-layer edge aggregation: one warp per node ----------------
__global__ __launch_bounds__(256) void k_agg(int parity,
    const float* __restrict__ x0,
    const float* __restrict__ relw,   // [NREL, D] for this layer
    const int* __restrict__ esrc,
    const int* __restrict__ etype,
    const float* __restrict__ ew)
{
    const float* xcur = parity ? g_xb : g_xa;
    int gt = blockIdx.x * blockDim.x + threadIdx.x;
    int n = gt >> 5;
    int lane = gt & 31;
    if (n >= NN) return;
    int d4 = lane * 4;

    float4 b = *(const float4*)(x0 + n * D + d4);   // boundary (self) message
    float sx = b.x, sy = b.y, sz = b.z, sw = b.w;
    float qx = b.x * b.x, qy = b.y * b.y, qz = b.z * b.z, qw = b.w * b.w;
    float Mx = b.x, My = b.y, Mz = b.z, Mw = b.w;
    float mx = b.x, my = b.y, mz = b.z, mw = b.w;

    int beg = g_rowstart[n], end = g_rowstart[n + 1];
    for (int i = beg; i < end; i++) {
        int e = g_perm[i];
        int s = esrc[e];
        int t = etype[e];
        float w = ew[e];
        float4 xv = *(const float4*)(xcur + s * D + d4);
        float4 rv = *(const float4*)(relw + t * D + d4);
        float m;
        m = xv.x * rv.x * w; sx += m; qx += m * m; Mx = fmaxf(Mx, m); mx = fminf(mx, m);
        m = xv.y * rv.y * w; sy += m; qy += m * m; My = fmaxf(My, m); my = fminf(my, m);
        m = xv.z * rv.z * w; sz += m; qz += m * m; Mz = fmaxf(Mz, m); mz = fminf(mz, m);
        m = xv.w * rv.w * w; sw += m; qw += m * m; Mw = fmaxf(Mw, m); mw = fminf(mw, m);
    }
    float dinv = 1.0f / ((float)(end - beg) + 1.0f);
    float ex = sx * dinv, ey = sy * dinv, ez = sz * dinv, ew2 = sw * dinv;
    float vx = sqrtf(fmaxf(qx * dinv - ex * ex, 1e-6f));
    float vy = sqrtf(fmaxf(qy * dinv - ey * ey, 1e-6f));
    float vz = sqrtf(fmaxf(qz * dinv - ez * ez, 1e-6f));
    float vw = sqrtf(fmaxf(qw * dinv - ew2 * ew2, 1e-6f));
    long off = (long)n * D + d4;
    *(float4*)(g_mean + off) = make_float4(ex, ey, ez, ew2);
    *(float4*)(g_fmax + off) = make_float4(Mx, My, Mz, Mw);
    *(float4*)(g_fmin + off) = make_float4(mx, my, mz, mw);
    *(float4*)(g_fstd + off) = make_float4(vx, vy, vz, vw);
}

// ---------------- GEMM [50000 x 1664] @ [1664 x 128] + bias + LN + ReLU + residual ----------------
__global__ __launch_bounds__(256) void k_gemm(int parity,
    const float* __restrict__ W,      // [1664, 128]
    const float* __restrict__ bias,
    const float* __restrict__ lng,
    const float* __restrict__ lnb)
{
    const float* xcur = parity ? g_xb : g_xa;
    float* xnext = parity ? g_xa : g_xb;
    __shared__ float As[TM][TKC + 4];
    __shared__ float Bs[TKC][D];

    int tid = threadIdx.x;
    int m0 = blockIdx.x * TM;
    int cx = tid & 15;          // column group
    int cy = tid >> 4;          // row group (0..15)
    int c0 = cx * 4;
    int c1 = 64 + cx * 4;       // split columns to keep shared reads conflict-free

    unsigned long long acc[8][4];
    unsigned long long z = pk2(0.f, 0.f);
    #pragma unroll
    for (int i = 0; i < 8; i++)
        #pragma unroll
        for (int j = 0; j < 4; j++) acc[i][j] = z;

    for (int ci = 0; ci < KTOT / TKC; ci++) {
        int k0 = ci * TKC;
        int bi = k0 >> 7;                       // 0..12  (scaler*4 + feat; 12 = raw x)
        int sidx = bi < 12 ? (bi >> 2) : 3;
        const float* buf;
        if (bi >= 12) buf = xcur;
        else {
            int f = bi & 3;
            buf = (f == 0) ? g_mean : (f == 1) ? g_fmax : (f == 2) ? g_fmin : g_fstd;
        }
        int kbase = k0 & 127;

        // A tile: 128 rows x 32 k, synthesized = feat * scale
        #pragma unroll
        for (int j = 0; j < 4; j++) {
            int id = tid + j * 256;
            int row = id >> 3;
            int node = m0 + row;
            int q = (id & 7) * 4;
            float4 v = make_float4(0.f, 0.f, 0.f, 0.f);
            float sc = 0.f;
            if (node < NN) {
                v = *(const float4*)(buf + (long)node * D + kbase + q);
                sc = g_scales[node * 4 + sidx];
            }
            *(float4*)&As[row][q] = make_float4(v.x * sc, v.y * sc, v.z * sc, v.w * sc);
        }
        // B tile: 32 x 128
        #pragma unroll
        for (int j = 0; j < 4; j++) {
            int id = tid + j * 256;
            int r = id >> 5;
            int c4 = (id & 31) * 4;
            *(float4*)&Bs[r][c4] = *(const float4*)(W + (long)(k0 + r) * D + c4);
        }
        __syncthreads();

        #pragma unroll 8
        for (int kk = 0; kk < TKC; kk++) {
            float4 b0 = *(float4*)&Bs[kk][c0];
            float4 b1 = *(float4*)&Bs[kk][c1];
            unsigned long long bp0 = pk2(b0.x, b0.y), bp1 = pk2(b0.z, b0.w);
            unsigned long long bp2 = pk2(b1.x, b1.y), bp3 = pk2(b1.z, b1.w);
            #pragma unroll
            for (int r = 0; r < 8; r++) {
                float a = As[cy * 8 + r][kk];
                unsigned long long a2 = pk2(a, a);
                fma2(acc[r][0], a2, bp0);
                fma2(acc[r][1], a2, bp1);
                fma2(acc[r][2], a2, bp2);
                fma2(acc[r][3], a2, bp3);
            }
        }
        __syncthreads();
    }

    // ---- epilogue: bias + layernorm + relu + residual ----
    float4 bi0 = *(const float4*)(bias + c0);
    float4 bi1 = *(const float4*)(bias + c1);
    float4 g0 = *(const float4*)(lng + c0);
    float4 g1 = *(const float4*)(lng + c1);
    float4 be0 = *(const float4*)(lnb + c0);
    float4 be1 = *(const float4*)(lnb + c1);

    #pragma unroll
    for (int r = 0; r < 8; r++) {
        int node = m0 + cy * 8 + r;
        float v[8];
        float2 t;
        t = up2(acc[r][0]); v[0] = t.x; v[1] = t.y;
        t = up2(acc[r][1]); v[2] = t.x; v[3] = t.y;
        t = up2(acc[r][2]); v[4] = t.x; v[5] = t.y;
        t = up2(acc[r][3]); v[6] = t.x; v[7] = t.y;
        v[0] += bi0.x; v[1] += bi0.y; v[2] += bi0.z; v[3] += bi0.w;
        v[4] += bi1.x; v[5] += bi1.y; v[6] += bi1.z; v[7] += bi1.w;
        float s = 0.f, sq = 0.f;
        #pragma unroll
        for (int j = 0; j < 8; j++) { s += v[j]; sq += v[j] * v[j]; }
        // reduce across the 16-lane group holding this row's 128 cols
        #pragma unroll
        for (int o = 1; o < 16; o <<= 1) {
            s  += __shfl_xor_sync(0xffffffffu, s,  o);
            sq += __shfl_xor_sync(0xffffffffu, sq, o);
        }
        float mean = s * (1.0f / 128.0f);
        float var = sq * (1.0f / 128.0f) - mean * mean;
        float inv = rsqrtf(var + 1e-5f);
        if (node < NN) {
            float4 r0 = *(const float4*)(xcur + (long)node * D + c0);
            float4 r1 = *(const float4*)(xcur + (long)node * D + c1);
            float o0 = fmaxf((v[0] - mean) * inv * g0.x + be0.x, 0.f) + r0.x;
            float o1 = fmaxf((v[1] - mean) * inv * g0.y + be0.y, 0.f) + r0.y;
            float o2 = fmaxf((v[2] - mean) * inv * g0.z + be0.z, 0.f) + r0.z;
            float o3 = fmaxf((v[3] - mean) * inv * g0.w + be0.w, 0.f) + r0.w;
            float o4 = fmaxf((v[4] - mean) * inv * g1.x + be1.x, 0.f) + r1.x;
            float o5 = fmaxf((v[5] - mean) * inv * g1.y + be1.y, 0.f) + r1.y;
            float o6 = fmaxf((v[6] - mean) * inv * g1.z + be1.z, 0.f) + r1.z;
            float o7 = fmaxf((v[7] - mean) * inv * g1.w + be1.w, 0.f) + r1.w;
            *(float4*)(xnext + (long)node * D + c0) = make_float4(o0, o1, o2, o3);
            *(float4*)(xnext + (long)node * D + c1) = make_float4(o4, o5, o6, o7);
        }
    }
}

// ---------------- final distmult scoring ----------------
__global__ __launch_bounds__(256) void k_score(
    const float* __restrict__ qw,
    const int* __restrict__ src,
    const int* __restrict__ rel,
    const int* __restrict__ dst,
    float* __restrict__ out)
{
    int gt = blockIdx.x * blockDim.x + threadIdx.x;
    int w = gt >> 5;
    int lane = gt & 31;
    if (w >= QB * QK) return;
    int s = src[w], r = rel[w], d = dst[w];
    int off = lane * 4;
    float4 a = *(const float4*)(g_xa + (long)s * D + off);
    float4 q = *(const float4*)(qw + (long)r * D + off);
    float4 b = *(const float4*)(g_xa + (long)d * D + off);
    float v = a.x * q.x * b.x + a.y * q.y * b.y + a.z * q.z * b.z + a.w * q.w * b.w;
    #pragma unroll
    for (int o = 16; o > 0; o >>= 1) v += __shfl_xor_sync(0xffffffffu, v, o);
    if (lane == 0) out[w] = v;
}

// ---------------- launch ----------------
extern "C" void kernel_launch(void* const* d_in, const int* in_sizes, int n_in,
                              void* d_out, int out_size) {
    const float* x0    = (const float*)d_in[0];
    const int*   eidx  = (const int*)  d_in[1];
    const int*   etype = (const int*)  d_in[2];
    const float* ew    = (const float*)d_in[3];
    const float* relw  = (const float*)d_in[4];
    const float* linw  = (const float*)d_in[5];
    const float* linb  = (const float*)d_in[6];
    const float* lng   = (const float*)d_in[7];
    const float* lnb   = (const float*)d_in[8];
    const float* qw    = (const float*)d_in[9];
    const int*   src   = (const int*)  d_in[10];
    const int*   rel   = (const int*)  d_in[11];
    const int*   dst   = (const int*)  d_in[12];
    float* out = (float*)d_out;

    const int* esrc = eidx;
    const int* edst = eidx + NE;

    k_init<<<(NN + 255) / 256, 256>>>();
    k_hist<<<(NE + 255) / 256, 256>>>(edst);
    k_scan<<<1, 1024>>>();
    k_scatter<<<(NE + 255) / 256, 256>>>(edst);
    k_logsum<<<(NN + 255) / 256, 256>>>();
    k_scales<<<(NN + 255) / 256, 256>>>();
    k_copy<<<(NN * D / 4 + 255) / 256, 256>>>(x0);

    for (int l = 0; l < NL; l++) {
        int parity = l & 1;
        k_agg<<<(NN * 32 + 255) / 256, 256>>>(parity, x0, relw + (long)l * NREL * D,
                                              esrc, etype, ew);
        k_gemm<<<(NN + TM - 1) / TM, 256>>>(parity, linw + (long)l * KTOT * D,
                                            linb + (long)l * D, lng + (long)l * D,
                                            lnb + (long)l * D);
    }

    k_score<<<(QB * QK * 32 + 255) / 256, 256>>>(qw, src, rel, dst, out);
}

// round 3
// speedup vs baseline: 1.5105x; 1.5105x over previous
#include <cuda_runtime.h>
#include <cuda_bf16.h>
#include <cstdint>

#define NN   50000
#define NE   500000
#define D    128
#define NREL 51
#define NL   4
#define QB   1024
#define QK   32
#define KTOT 1664     // 13 * D
#define NCHK 52       // K chunks of 32

// ---------------- static device scratch ----------------
__device__ int   g_deg[NN];
__device__ int   g_rowstart[NN + 1];
__device__ int   g_cursor[NN];
__device__ int   g_perm[NE];
__device__ float g_scales[NN * 4];
__device__ float g_logsum;
__device__ float g_mean[NN * D];
__device__ float g_fmax[NN * D];
__device__ float g_fmin[NN * D];
__device__ float g_fstd[NN * D];
__device__ float g_xa[NN * D];
__device__ float g_xb[NN * D];
__device__ __nv_bfloat16 g_wth[NL * D * KTOT];   // W^T hi  [l][n][k]
__device__ __nv_bfloat16 g_wtl[NL * D * KTOT];   // W^T lo

// ---------------- helpers ----------------
__device__ __forceinline__ uint32_t smem_u32(const void* p) {
    uint32_t a;
    asm("{ .reg .u64 t; cvta.to.shared.u64 t, %1; cvt.u32.u64 %0, t; }" : "=r"(a) : "l"(p));
    return a;
}
__device__ __forceinline__ uint32_t pkbf(__nv_bfloat16 a, __nv_bfloat16 b) {
    __nv_bfloat162 t = __halves2bfloat162(a, b);
    return *reinterpret_cast<uint32_t*>(&t);
}
__device__ __forceinline__ void ldsm_x4(uint32_t addr, uint32_t* r) {
    asm volatile("ldmatrix.sync.aligned.m8n8.x4.shared.b16 {%0,%1,%2,%3}, [%4];"
        : "=r"(r[0]), "=r"(r[1]), "=r"(r[2]), "=r"(r[3]) : "r"(addr));
}
__device__ __forceinline__ void mma_bf16(float* c, const uint32_t* a, const uint32_t* b) {
    asm volatile("mma.sync.aligned.m16n8k16.row.col.f32.bf16.bf16.f32 "
        "{%0,%1,%2,%3}, {%4,%5,%6,%7}, {%8,%9}, {%0,%1,%2,%3};"
        : "+f"(c[0]), "+f"(c[1]), "+f"(c[2]), "+f"(c[3])
        : "r"(a[0]), "r"(a[1]), "r"(a[2]), "r"(a[3]), "r"(b[0]), "r"(b[1]));
}

// ---------------- CSR build ----------------
__global__ void k_init() {
    int i = blockIdx.x * blockDim.x + threadIdx.x;
    if (i < NN) g_deg[i] = 0;
    if (i == 0) g_logsum = 0.f;
}
__global__ void k_hist(const int* __restrict__ edst) {
    int e = blockIdx.x * blockDim.x + threadIdx.x;
    if (e < NE) atomicAdd(&g_deg[edst[e]], 1);
}
__global__ void k_scan() {   // 1 block, 1024 threads, warp-shuffle scan
    __shared__ int wsum[32];
    int tid = threadIdx.x;
    const int CH = (NN + 1023) / 1024;   // 49
    int base = tid * CH;
    int local = 0;
    for (int i = 0; i < CH; i++) {
        int idx = base + i;
        if (idx < NN) local += g_deg[idx];
    }
    int lane = tid & 31, w = tid >> 5;
    int pre = local;
    #pragma unroll
    for (int o = 1; o < 32; o <<= 1) {
        int t = __shfl_up_sync(0xffffffffu, pre, o);
        if (lane >= o) pre += t;
    }
    if (lane == 31) wsum[w] = pre;
    __syncthreads();
    if (w == 0) {
        int v = wsum[lane];
        #pragma unroll
        for (int o = 1; o < 32; o <<= 1) {
            int t = __shfl_up_sync(0xffffffffu, v, o);
            if (lane >= o) v += t;
        }
        wsum[lane] = v;
    }
    __syncthreads();
    int run = pre - local + (w > 0 ? wsum[w - 1] : 0);
    for (int i = 0; i < CH; i++) {
        int idx = base + i;
        if (idx < NN) {
            int d = g_deg[idx];
            g_rowstart[idx] = run;
            g_cursor[idx] = run;
            run += d;
        }
    }
    if (tid == 0) g_rowstart[NN] = NE;
}
__global__ void k_scatter(const int* __restrict__ edst) {
    int e = blockIdx.x * blockDim.x + threadIdx.x;
    if (e < NE) {
        int p = atomicAdd(&g_cursor[edst[e]], 1);
        g_perm[p] = e;
    }
}
__global__ void k_logsum() {
    int i = blockIdx.x * blockDim.x + threadIdx.x;
    float v = 0.f;
    if (i < NN) v = logf((float)g_deg[i] + 1.0f);
    #pragma unroll
    for (int o = 16; o > 0; o >>= 1) v += __shfl_xor_sync(0xffffffffu, v, o);
    if ((threadIdx.x & 31) == 0 && v != 0.f) atomicAdd(&g_logsum, v);
}
__global__ void k_scales() {
    int i = blockIdx.x * blockDim.x + threadIdx.x;
    if (i >= NN) return;
    float mean = g_logsum * (1.0f / (float)NN);
    float s = logf((float)g_deg[i] + 1.0f) / mean;
    g_scales[i * 4 + 0] = 1.0f;
    g_scales[i * 4 + 1] = s;
    g_scales[i * 4 + 2] = 1.0f / fmaxf(s, 1e-2f);
    g_scales[i * 4 + 3] = 1.0f;
}
__global__ void k_copy(const float* __restrict__ x0) {
    int i = blockIdx.x * blockDim.x + threadIdx.x;
    if (i < NN * D / 4) ((float4*)g_xa)[i] = ((const float4*)x0)[i];
}

// ---------------- W^T + bf16 hi/lo split ----------------
__global__ void k_wsplit(const float* __restrict__ linw) {
    long i = (long)blockIdx.x * blockDim.x + threadIdx.x;
    if (i >= (long)NL * D * KTOT) return;
    int k = (int)(i % KTOT);
    long rest = i / KTOT;
    int n = (int)(rest % D);
    int l = (int)(rest / D);
    float w = linw[(long)l * KTOT * D + (long)k * D + n];
    __nv_bfloat16 h = __float2bfloat16(w);
    float r = w - __bfloat162float(h);
    g_wth[i] = h;
    g_wtl[i] = __float2bfloat16(r);
}

// ---------------- per-layer edge aggregation ----------------
__global__ __launch_bounds__(256) void k_agg(int parity,
    const float* __restrict__ x0,
    const float* __restrict__ relw,
    const int* __restrict__ esrc,
    const int* __restrict__ etype,
    const float* __restrict__ ew)
{
    const float* xcur = parity ? g_xb : g_xa;
    int gt = blockIdx.x * blockDim.x + threadIdx.x;
    int n = gt >> 5;
    int lane = gt & 31;
    if (n >= NN) return;
    int d4 = lane * 4;

    float4 b = *(const float4*)(x0 + n * D + d4);
    float sx = b.x, sy = b.y, sz = b.z, sw = b.w;
    float qx = b.x * b.x, qy = b.y * b.y, qz = b.z * b.z, qw = b.w * b.w;
    float Mx = b.x, My = b.y, Mz = b.z, Mw = b.w;
    float mx = b.x, my = b.y, mz = b.z, mw = b.w;

    int beg = g_rowstart[n], end = g_rowstart[n + 1];
    for (int i = beg; i < end; i++) {
        int e = g_perm[i];
        int s = esrc[e];
        int t = etype[e];
        float w = ew[e];
        float4 xv = *(const float4*)(xcur + s * D + d4);
        float4 rv = *(const float4*)(relw + t * D + d4);
        float m;
        m = xv.x * rv.x * w; sx += m; qx += m * m; Mx = fmaxf(Mx, m); mx = fminf(mx, m);
        m = xv.y * rv.y * w; sy += m; qy += m * m; My = fmaxf(My, m); my = fminf(my, m);
        m = xv.z * rv.z * w; sz += m; qz += m * m; Mz = fmaxf(Mz, m); mz = fminf(mz, m);
        m = xv.w * rv.w * w; sw += m; qw += m * m; Mw = fmaxf(Mw, m); mw = fminf(mw, m);
    }
    float dinv = 1.0f / ((float)(end - beg) + 1.0f);
    float ex = sx * dinv, ey = sy * dinv, ez = sz * dinv, ew2 = sw * dinv;
    float vx = sqrtf(fmaxf(qx * dinv - ex * ex, 1e-6f));
    float vy = sqrtf(fmaxf(qy * dinv - ey * ey, 1e-6f));
    float vz = sqrtf(fmaxf(qz * dinv - ez * ez, 1e-6f));
    float vw = sqrtf(fmaxf(qw * dinv - ew2 * ew2, 1e-6f));
    long off = (long)n * D + d4;
    *(float4*)(g_mean + off) = make_float4(ex, ey, ez, ew2);
    *(float4*)(g_fmax + off) = make_float4(Mx, My, Mz, Mw);
    *(float4*)(g_fmin + off) = make_float4(mx, my, mz, mw);
    *(float4*)(g_fstd + off) = make_float4(vx, vy, vz, vw);
}

// ---------------- mma.sync bf16 3-pass GEMM ----------------
// smem: [0..1536) bias|g|b, [1536..3584) LN reduction, [4096 + st*40960): tiles
// tile stage: Ah(10240) Al(10240) Bh(10240) Bl(10240), row stride 80 B (32 bf16 + 8 pad)
#define SM_RED   1536
#define SM_TILES 4096
#define ST_STRIDE 40960
#define OFF_AH 0
#define OFF_AL 10240
#define OFF_BH 20480
#define OFF_BL 30720
#define ROWB 80
#define GEMM_SMEM (SM_TILES + 2 * ST_STRIDE)

__global__ __launch_bounds__(256, 1) void k_gemm(int parity, long lwoff,
    const float* __restrict__ bias,
    const float* __restrict__ lng,
    const float* __restrict__ lnb)
{
    extern __shared__ char smem[];
    const float* xcur = parity ? g_xb : g_xa;
    float* xnext = parity ? g_xa : g_xb;

    uint32_t sb = smem_u32(smem);
    int tid = threadIdx.x;
    int wid = tid >> 5;
    int lane = tid & 31;
    int m0 = blockIdx.x * 128;

    float* smf = (float*)smem;
    if (tid < 128) {
        smf[tid] = bias[tid];
        smf[128 + tid] = lng[tid];
        smf[256 + tid] = lnb[tid];
    }

    int row = tid >> 1;            // fill row 0..127
    int half = tid & 1;            // fill k half (16 elems)
    int node = m0 + row;
    int kloc = half * 16;

    // fill one K-chunk (c) into stage st
    auto fill = [&](int c, int st) {
        char* tiles = smem + SM_TILES + st * ST_STRIDE;
        int bi = c >> 2;
        int kb = (c & 3) * 32;
        int sidx = (bi < 12) ? (bi >> 2) : 3;
        const float* buf;
        if (bi >= 12) buf = xcur;
        else {
            int f = bi & 3;
            buf = (f == 0) ? g_mean : (f == 1) ? g_fmax : (f == 2) ? g_fmin : g_fstd;
        }
        float s = 0.f;
        const float* src = nullptr;
        if (node < NN) {
            s = g_scales[node * 4 + sidx];
            src = buf + (long)node * D + kb + kloc;
        }
        uint32_t hw[8], lw[8];
        #pragma unroll
        for (int j = 0; j < 4; j++) {
            float4 v = src ? *(const float4*)(src + j * 4) : make_float4(0.f, 0.f, 0.f, 0.f);
            float a0 = v.x * s, a1 = v.y * s, a2 = v.z * s, a3 = v.w * s;
            __nv_bfloat16 h0 = __float2bfloat16(a0), h1 = __float2bfloat16(a1);
            __nv_bfloat16 h2 = __float2bfloat16(a2), h3 = __float2bfloat16(a3);
            hw[j * 2 + 0] = pkbf(h0, h1);
            hw[j * 2 + 1] = pkbf(h2, h3);
            lw[j * 2 + 0] = pkbf(__float2bfloat16(a0 - __bfloat162float(h0)),
                                 __float2bfloat16(a1 - __bfloat162float(h1)));
            lw[j * 2 + 1] = pkbf(__float2bfloat16(a2 - __bfloat162float(h2)),
                                 __float2bfloat16(a3 - __bfloat162float(h3)));
        }
        char* ah = tiles + OFF_AH + row * ROWB + kloc * 2;
        char* al = tiles + OFF_AL + row * ROWB + kloc * 2;
        *(uint4*)(ah)      = make_uint4(hw[0], hw[1], hw[2], hw[3]);
        *(uint4*)(ah + 16) = make_uint4(hw[4], hw[5], hw[6], hw[7]);
        *(uint4*)(al)      = make_uint4(lw[0], lw[1], lw[2], lw[3]);
        *(uint4*)(al + 16) = make_uint4(lw[4], lw[5], lw[6], lw[7]);
        // B (pre-split W^T [n][k])
        const __nv_bfloat16* wh = g_wth + lwoff + (long)row * KTOT + c * 32 + kloc;
        const __nv_bfloat16* wl = g_wtl + lwoff + (long)row * KTOT + c * 32 + kloc;
        char* bh = tiles + OFF_BH + row * ROWB + kloc * 2;
        char* bl = tiles + OFF_BL + row * ROWB + kloc * 2;
        *(uint4*)(bh)      = *(const uint4*)(wh);
        *(uint4*)(bh + 16) = *(const uint4*)(wh + 8);
        *(uint4*)(bl)      = *(const uint4*)(wl);
        *(uint4*)(bl + 16) = *(const uint4*)(wl + 8);
    };

    int wm = (wid & 3) * 32;
    int wn = (wid >> 2) * 64;
    int l2 = lane & 3, l4 = lane >> 2;

    float acc[2][8][4];
    #pragma unroll
    for (int t = 0; t < 2; t++)
        #pragma unroll
        for (int j = 0; j < 8; j++)
            #pragma unroll
            for (int i = 0; i < 4; i++) acc[t][j][i] = 0.f;

    // ldmatrix lane-address components (row parts)
    int arow0 = (lane & 7) + ((lane >> 3) & 1) * 8;   // A: within m16
    int aseg  = (lane >> 4) * 16;                     // A: k half (bytes)
    int brow0 = (lane & 7) + (lane >> 4) * 8;         // B: within n16
    int bseg  = ((lane >> 3) & 1) * 16;               // B: k half (bytes)

    fill(0, 0);
    __syncthreads();

    for (int c = 0; c < NCHK; c++) {
        int st = c & 1;
        if (c + 1 < NCHK) fill(c + 1, st ^ 1);
        uint32_t tb = sb + SM_TILES + st * ST_STRIDE;
        #pragma unroll
        for (int ks = 0; ks < 2; ks++) {
            int k0b = ks * 32;   // 16 elems * 2B
            uint32_t ah[2][4], alr[2][4], bb[4][4];
            #pragma unroll
            for (int t = 0; t < 2; t++) {
                uint32_t ra = tb + OFF_AH + (uint32_t)(wm + t * 16 + arow0) * ROWB + k0b + aseg;
                ldsm_x4(ra, ah[t]);
                uint32_t rl = ra + (OFF_AL - OFF_AH);
                ldsm_x4(rl, alr[t]);
            }
            #pragma unroll
            for (int p = 0; p < 4; p++) {
                uint32_t rb = tb + OFF_BH + (uint32_t)(wn + p * 16 + brow0) * ROWB + k0b + bseg;
                ldsm_x4(rb, bb[p]);
            }
            #pragma unroll
            for (int t = 0; t < 2; t++)
                #pragma unroll
                for (int p = 0; p < 4; p++) {
                    mma_bf16(acc[t][2 * p],     ah[t],  &bb[p][0]);
                    mma_bf16(acc[t][2 * p + 1], ah[t],  &bb[p][2]);
                }
            #pragma unroll
            for (int t = 0; t < 2; t++)
                #pragma unroll
                for (int p = 0; p < 4; p++) {
                    mma_bf16(acc[t][2 * p],     alr[t], &bb[p][0]);
                    mma_bf16(acc[t][2 * p + 1], alr[t], &bb[p][2]);
                }
            #pragma unroll
            for (int p = 0; p < 4; p++) {
                uint32_t rb = tb + OFF_BL + (uint32_t)(wn + p * 16 + brow0) * ROWB + k0b + bseg;
                ldsm_x4(rb, bb[p]);
            }
            #pragma unroll
            for (int t = 0; t < 2; t++)
                #pragma unroll
                for (int p = 0; p < 4; p++) {
                    mma_bf16(acc[t][2 * p],     ah[t], &bb[p][0]);
                    mma_bf16(acc[t][2 * p + 1], ah[t], &bb[p][2]);
                }
        }
        __syncthreads();
    }

    // ---- epilogue: bias + LN + relu + residual ----
    float* red = (float*)(smem + SM_RED);   // [128][4]: {sum0,sq0,sum1,sq1}
    float s[4] = {0.f, 0.f, 0.f, 0.f}, q[4] = {0.f, 0.f, 0.f, 0.f};
    #pragma unroll
    for (int t = 0; t < 2; t++)
        #pragma unroll
        for (int j = 0; j < 8; j++) {
            int col = wn + j * 8 + l2 * 2;
            float b0 = smf[col], b1 = smf[col + 1];
            acc[t][j][0] += b0; acc[t][j][1] += b1;
            acc[t][j][2] += b0; acc[t][j][3] += b1;
            s[2 * t]     += acc[t][j][0] + acc[t][j][1];
            q[2 * t]     += acc[t][j][0] * acc[t][j][0] + acc[t][j][1] * acc[t][j][1];
            s[2 * t + 1] += acc[t][j][2] + acc[t][j][3];
            q[2 * t + 1] += acc[t][j][2] * acc[t][j][2] + acc[t][j][3] * acc[t][j][3];
        }
    #pragma unroll
    for (int i = 0; i < 4; i++) {
        s[i] += __shfl_xor_sync(0xffffffffu, s[i], 1);
        q[i] += __shfl_xor_sync(0xffffffffu, q[i], 1);
        s[i] += __shfl_xor_sync(0xffffffffu, s[i], 2);
        q[i] += __shfl_xor_sync(0xffffffffu, q[i], 2);
    }
    int nh = wid >> 2;   // n-half
    if (l2 == 0) {
        #pragma unroll
        for (int i = 0; i < 4; i++) {
            int rw = wm + i * 8 + l4;
            red[rw * 4 + nh * 2 + 0] = s[i];
            red[rw * 4 + nh * 2 + 1] = q[i];
        }
    }
    __syncthreads();
    float mean[4], inv[4];
    #pragma unroll
    for (int i = 0; i < 4; i++) {
        int rw = wm + i * 8 + l4;
        float tot  = red[rw * 4 + 0] + red[rw * 4 + 2];
        float totq = red[rw * 4 + 1] + red[rw * 4 + 3];
        float mu = tot * (1.0f / 128.0f);
        float var = totq * (1.0f / 128.0f) - mu * mu;
        mean[i] = mu;
        inv[i] = rsqrtf(var + 1e-5f);
    }
    #pragma unroll
    for (int t = 0; t < 2; t++) {
        #pragma unroll
        for (int half2 = 0; half2 < 2; half2++) {
            int ri = 2 * t + half2;
            int nodeR = m0 + wm + ri * 8 + l4;
            if (nodeR >= NN) continue;
            float mu = mean[ri], iv = inv[ri];
            #pragma unroll
            for (int j = 0; j < 8; j++) {
                int col = wn + j * 8 + l2 * 2;
                float g0 = smf[128 + col], g1 = smf[128 + col + 1];
                float e0 = smf[256 + col], e1 = smf[256 + col + 1];
                float2 res = *(const float2*)(xcur + (long)nodeR * D + col);
                float v0 = acc[t][j][half2 * 2 + 0];
                float v1 = acc[t][j][half2 * 2 + 1];
                float o0 = fmaxf((v0 - mu) * iv * g0 + e0, 0.f) + res.x;
                float o1 = fmaxf((v1 - mu) * iv * g1 + e1, 0.f) + res.y;
                *(float2*)(xnext + (long)nodeR * D + col) = make_float2(o0, o1);
            }
        }
    }
}

// ---------------- final distmult scoring ----------------
__global__ __launch_bounds__(256) void k_score(
    const float* __restrict__ qw,
    const int* __restrict__ src,
    const int* __restrict__ rel,
    const int* __restrict__ dst,
    float* __restrict__ out)
{
    int gt = blockIdx.x * blockDim.x + threadIdx.x;
    int w = gt >> 5;
    int lane = gt & 31;
    if (w >= QB * QK) return;
    int s = src[w], r = rel[w], d = dst[w];
    int off = lane * 4;
    float4 a = *(const float4*)(g_xa + (long)s * D + off);
    float4 q = *(const float4*)(qw + (long)r * D + off);
    float4 b = *(const float4*)(g_xa + (long)d * D + off);
    float v = a.x * q.x * b.x + a.y * q.y * b.y + a.z * q.z * b.z + a.w * q.w * b.w;
    #pragma unroll
    for (int o = 16; o > 0; o >>= 1) v += __shfl_xor_sync(0xffffffffu, v, o);
    if (lane == 0) out[w] = v;
}

// ---------------- launch ----------------
extern "C" void kernel_launch(void* const* d_in, const int* in_sizes, int n_in,
                              void* d_out, int out_size) {
    const float* x0    = (const float*)d_in[0];
    const int*   eidx  = (const int*)  d_in[1];
    const int*   etype = (const int*)  d_in[2];
    const float* ew    = (const float*)d_in[3];
    const float* relw  = (const float*)d_in[4];
    const float* linw  = (const float*)d_in[5];
    const float* linb  = (const float*)d_in[6];
    const float* lng   = (const float*)d_in[7];
    const float* lnb   = (const float*)d_in[8];
    const float* qw    = (const float*)d_in[9];
    const int*   src   = (const int*)  d_in[10];
    const int*   rel   = (const int*)  d_in[11];
    const int*   dst   = (const int*)  d_in[12];
    float* out = (float*)d_out;

    const int* esrc = eidx;
    const int* edst = eidx + NE;

    static int smem_set = 0;
    if (!smem_set) {
        cudaFuncSetAttribute(k_gemm, cudaFuncAttributeMaxDynamicSharedMemorySize, GEMM_SMEM);
        smem_set = 1;
    }

    k_init<<<(NN + 255) / 256, 256>>>();
    k_hist<<<(NE + 255) / 256, 256>>>(edst);
    k_scan<<<1, 1024>>>();
    k_scatter<<<(NE + 255) / 256, 256>>>(edst);
    k_logsum<<<(NN + 255) / 256, 256>>>();
    k_scales<<<(NN + 255) / 256, 256>>>();
    k_copy<<<(NN * D / 4 + 255) / 256, 256>>>(x0);
    k_wsplit<<<((long)NL * D * KTOT + 255) / 256, 256>>>(linw);

    for (int l = 0; l < NL; l++) {
        int parity = l & 1;
        k_agg<<<(NN * 32 + 255) / 256, 256>>>(parity, x0, relw + (long)l * NREL * D,
                                              esrc, etype, ew);
        k_gemm<<<(NN + 127) / 128, 256, GEMM_SMEM>>>(parity, (long)l * D * KTOT,
                                                     linb + (long)l * D, lng + (long)l * D,
                                                     lnb + (long)l * D);
    }

    k_score<<<(QB * QK * 32 + 255) / 256, 256>>>(qw, src, rel, dst, out);
}

// round 5
// speedup vs baseline: 1.7329x; 1.1472x over previous
#include <cuda_runtime.h>
#include <cuda_bf16.h>
#include <cstdint>

#define NN   50000
#define NE   500000
#define D    128
#define NREL 51
#define NL   4
#define QB   1024
#define QK   32
#define KTOT 1664     // 13 * D
#define NCHK 52       // K chunks of 32

// ---------------- static device scratch ----------------
__device__ int   g_deg[NN];
__device__ int   g_rowstart[NN + 1];
__device__ int   g_cursor[NN];
__device__ int2  g_es[NE];            // sorted (src, type)
__device__ float g_ew[NE];            // sorted weight
__device__ float g_scales[NN * 4];
__device__ float g_logsum;
__device__ float g_xa[NN * D];
__device__ float g_xb[NN * D];
__device__ __nv_bfloat16 g_ah[(long)NN * KTOT];   // A hi  (premultiplied, bf16)
__device__ __nv_bfloat16 g_al[(long)NN * KTOT];   // A lo
__device__ __nv_bfloat16 g_wth[NL * D * KTOT];    // W^T hi [l][n][k]
__device__ __nv_bfloat16 g_wtl[NL * D * KTOT];    // W^T lo

// ---------------- helpers ----------------
__device__ __forceinline__ uint32_t smem_u32(const void* p) {
    uint32_t a;
    asm("{ .reg .u64 t; cvta.to.shared.u64 t, %1; cvt.u32.u64 %0, t; }" : "=r"(a) : "l"(p));
    return a;
}
__device__ __forceinline__ uint32_t pkbf(__nv_bfloat16 a, __nv_bfloat16 b) {
    __nv_bfloat162 t = __halves2bfloat162(a, b);
    return *reinterpret_cast<uint32_t*>(&t);
}
__device__ __forceinline__ void ldsm_x4(uint32_t addr, uint32_t* r) {
    asm volatile("ldmatrix.sync.aligned.m8n8.x4.shared.b16 {%0,%1,%2,%3}, [%4];"
        : "=r"(r[0]), "=r"(r[1]), "=r"(r[2]), "=r"(r[3]) : "r"(addr));
}
__device__ __forceinline__ void mma_bf16(float* c, const uint32_t* a, const uint32_t* b) {
    asm volatile("mma.sync.aligned.m16n8k16.row.col.f32.bf16.bf16.f32 "
        "{%0,%1,%2,%3}, {%4,%5,%6,%7}, {%8,%9}, {%0,%1,%2,%3};"
        : "+f"(c[0]), "+f"(c[1]), "+f"(c[2]), "+f"(c[3])
        : "r"(a[0]), "r"(a[1]), "r"(a[2]), "r"(a[3]), "r"(b[0]), "r"(b[1]));
}
#define CP16(dst, src, pbytes) \
    asm volatile("cp.async.cg.shared.global [%0], [%1], 16, %2;" \
        :: "r"(dst), "l"(src), "r"(pbytes))
#define CP_COMMIT() asm volatile("cp.async.commit_group;")
#define CP_WAIT(n)  asm volatile("cp.async.wait_group %0;" :: "n"(n))

// ---------------- CSR build ----------------
__global__ void k_init() {
    int i = blockIdx.x * blockDim.x + threadIdx.x;
    if (i < NN) g_deg[i] = 0;
    if (i == 0) g_logsum = 0.f;
}
__global__ void k_hist(const int* __restrict__ edst) {
    int e = blockIdx.x * blockDim.x + threadIdx.x;
    if (e < NE) atomicAdd(&g_deg[edst[e]], 1);
}
__global__ void k_scan() {   // 1 block, 1024 threads, warp-shuffle scan
    __shared__ int wsum[32];
    int tid = threadIdx.x;
    const int CH = (NN + 1023) / 1024;
    int base = tid * CH;
    int local = 0;
    for (int i = 0; i < CH; i++) {
        int idx = base + i;
        if (idx < NN) local += g_deg[idx];
    }
    int lane = tid & 31, w = tid >> 5;
    int pre = local;
    #pragma unroll
    for (int o = 1; o < 32; o <<= 1) {
        int t = __shfl_up_sync(0xffffffffu, pre, o);
        if (lane >= o) pre += t;
    }
    if (lane == 31) wsum[w] = pre;
    __syncthreads();
    if (w == 0) {
        int v = wsum[lane];
        #pragma unroll
        for (int o = 1; o < 32; o <<= 1) {
            int t = __shfl_up_sync(0xffffffffu, v, o);
            if (lane >= o) v += t;
        }
        wsum[lane] = v;
    }
    __syncthreads();
    int run = pre - local + (w > 0 ? wsum[w - 1] : 0);
    for (int i = 0; i < CH; i++) {
        int idx = base + i;
        if (idx < NN) {
            int d = g_deg[idx];
            g_rowstart[idx] = run;
            g_cursor[idx] = run;
            run += d;
        }
    }
    if (tid == 0) g_rowstart[NN] = NE;
}
__global__ void k_scatter(const int* __restrict__ esrc, const int* __restrict__ edst,
                          const int* __restrict__ etype, const float* __restrict__ ew) {
    int e = blockIdx.x * blockDim.x + threadIdx.x;
    if (e < NE) {
        int p = atomicAdd(&g_cursor[edst[e]], 1);
        g_es[p] = make_int2(esrc[e], etype[e]);
        g_ew[p] = ew[e];
    }
}
__global__ void k_logsum() {
    int i = blockIdx.x * blockDim.x + threadIdx.x;
    float v = 0.f;
    if (i < NN) v = logf((float)g_deg[i] + 1.0f);
    #pragma unroll
    for (int o = 16; o > 0; o >>= 1) v += __shfl_xor_sync(0xffffffffu, v, o);
    if ((threadIdx.x & 31) == 0 && v != 0.f) atomicAdd(&g_logsum, v);
}
__global__ void k_scales() {
    int i = blockIdx.x * blockDim.x + threadIdx.x;
    if (i >= NN) return;
    float mean = g_logsum * (1.0f / (float)NN);
    float s = logf((float)g_deg[i] + 1.0f) / mean;
    g_scales[i * 4 + 0] = 1.0f;
    g_scales[i * 4 + 1] = s;
    g_scales[i * 4 + 2] = 1.0f / fmaxf(s, 1e-2f);
    g_scales[i * 4 + 3] = 1.0f;
}
// copy x0 -> g_xa fp32, and bf16 hi/lo into A block 12
__global__ void k_copy(const float* __restrict__ x0) {
    int i = blockIdx.x * blockDim.x + threadIdx.x;
    if (i >= NN * 32) return;
    int node = i >> 5;
    int d4 = (i & 31) * 4;
    float4 v = *(const float4*)(x0 + (long)node * D + d4);
    *(float4*)(g_xa + (long)node * D + d4) = v;
    __nv_bfloat16 h0 = __float2bfloat16(v.x), h1 = __float2bfloat16(v.y);
    __nv_bfloat16 h2 = __float2bfloat16(v.z), h3 = __float2bfloat16(v.w);
    long aoff = (long)node * KTOT + 12 * 128 + d4;
    *(uint2*)(g_ah + aoff) = make_uint2(pkbf(h0, h1), pkbf(h2, h3));
    *(uint2*)(g_al + aoff) = make_uint2(
        pkbf(__float2bfloat16(v.x - __bfloat162float(h0)), __float2bfloat16(v.y - __bfloat162float(h1))),
        pkbf(__float2bfloat16(v.z - __bfloat162float(h2)), __float2bfloat16(v.w - __bfloat162float(h3))));
}

// ---------------- W^T + bf16 hi/lo split ----------------
__global__ void k_wsplit(const float* __restrict__ linw) {
    long i = (long)blockIdx.x * blockDim.x + threadIdx.x;
    if (i >= (long)NL * D * KTOT) return;
    int k = (int)(i % KTOT);
    long rest = i / KTOT;
    int n = (int)(rest % D);
    int l = (int)(rest / D);
    float w = linw[(long)l * KTOT * D + (long)k * D + n];
    __nv_bfloat16 h = __float2bfloat16(w);
    float r = w - __bfloat162float(h);
    g_wth[i] = h;
    g_wtl[i] = __float2bfloat16(r);
}

// ---------------- per-layer edge aggregation -> premultiplied bf16 A blocks ----------------
__global__ __launch_bounds__(256) void k_agg(int parity,
    const float* __restrict__ x0,
    const float* __restrict__ relw)
{
    const float* xcur = parity ? g_xb : g_xa;
    int gt = blockIdx.x * blockDim.x + threadIdx.x;
    int n = gt >> 5;
    int lane = gt & 31;
    if (n >= NN) return;
    int d4 = lane * 4;

    float4 b = *(const float4*)(x0 + (long)n * D + d4);
    float sx = b.x, sy = b.y, sz = b.z, sw = b.w;
    float qx = b.x * b.x, qy = b.y * b.y, qz = b.z * b.z, qw = b.w * b.w;
    float Mx = b.x, My = b.y, Mz = b.z, Mw = b.w;
    float mx = b.x, my = b.y, mz = b.z, mw = b.w;

    int beg = g_rowstart[n], end = g_rowstart[n + 1];
    for (int i = beg; i < end; i++) {
        int2 st = g_es[i];
        float w = g_ew[i];
        float4 xv = *(const float4*)(xcur + (long)st.x * D + d4);
        float4 rv = *(const float4*)(relw + (long)st.y * D + d4);
        float m;
        m = xv.x * rv.x * w; sx += m; qx += m * m; Mx = fmaxf(Mx, m); mx = fminf(mx, m);
        m = xv.y * rv.y * w; sy += m; qy += m * m; My = fmaxf(My, m); my = fminf(my, m);
        m = xv.z * rv.z * w; sz += m; qz += m * m; Mz = fmaxf(Mz, m); mz = fminf(mz, m);
        m = xv.w * rv.w * w; sw += m; qw += m * m; Mw = fmaxf(Mw, m); mw = fminf(mw, m);
    }
    float dinv = 1.0f / ((float)(end - beg) + 1.0f);
    float4 fv[4];
    float ex = sx * dinv, ey = sy * dinv, ez = sz * dinv, ew2 = sw * dinv;
    fv[0] = make_float4(ex, ey, ez, ew2);
    fv[1] = make_float4(Mx, My, Mz, Mw);
    fv[2] = make_float4(mx, my, mz, mw);
    fv[3] = make_float4(sqrtf(fmaxf(qx * dinv - ex * ex, 1e-6f)),
                        sqrtf(fmaxf(qy * dinv - ey * ey, 1e-6f)),
                        sqrtf(fmaxf(qz * dinv - ez * ez, 1e-6f)),
                        sqrtf(fmaxf(qw * dinv - ew2 * ew2, 1e-6f)));
    float sc1 = g_scales[n * 4 + 1];
    float sc2 = g_scales[n * 4 + 2];
    long base = (long)n * KTOT + d4;
    #pragma unroll
    for (int s = 0; s < 3; s++) {
        float fac = (s == 0) ? 1.0f : (s == 1 ? sc1 : sc2);
        #pragma unroll
        for (int f = 0; f < 4; f++) {
            float a0 = fv[f].x * fac, a1 = fv[f].y * fac;
            float a2 = fv[f].z * fac, a3 = fv[f].w * fac;
            __nv_bfloat16 h0 = __float2bfloat16(a0), h1 = __float2bfloat16(a1);
            __nv_bfloat16 h2 = __float2bfloat16(a2), h3 = __float2bfloat16(a3);
            long off = base + (s * 4 + f) * 128;
            *(uint2*)(g_ah + off) = make_uint2(pkbf(h0, h1), pkbf(h2, h3));
            *(uint2*)(g_al + off) = make_uint2(
                pkbf(__float2bfloat16(a0 - __bfloat162float(h0)), __float2bfloat16(a1 - __bfloat162float(h1))),
                pkbf(__float2bfloat16(a2 - __bfloat162float(h2)), __float2bfloat16(a3 - __bfloat162float(h3))));
        }
    }
}

// ---------------- mma.sync bf16 3-pass GEMM, cp.async fills ----------------
#define SM_RED   1536
#define SM_TILES 4096
#define ST_STRIDE 40960
#define OFF_AH 0
#define OFF_AL 10240
#define OFF_BH 20480
#define OFF_BL 30720
#define ROWB 80
#define GEMM_SMEM (SM_TILES + 2 * ST_STRIDE)

__global__ __launch_bounds__(256, 1) void k_gemm(int parity, long lwoff,
    const float* __restrict__ bias,
    const float* __restrict__ lng,
    const float* __restrict__ lnb)
{
    extern __shared__ char smem[];
    const float* xcur = parity ? g_xb : g_xa;
    float* xnext = parity ? g_xa : g_xb;

    uint32_t sb = smem_u32(smem);
    int tid = threadIdx.x;
    int wid = tid >> 5;
    int lane = tid & 31;
    int m0 = blockIdx.x * 128;

    float* smf = (float*)smem;
    if (tid < 128) {
        smf[tid] = bias[tid];
        smf[128 + tid] = lng[tid];
        smf[256 + tid] = lnb[tid];
    }

    int row = tid >> 1;            // 0..127
    int half = tid & 1;
    int node = m0 + row;
    uint32_t avalid = (node < NN) ? 16u : 0u;

    // cp.async one K-chunk into stage st
    auto copy_chunk = [&](int c, int st) {
        uint32_t tb = sb + SM_TILES + st * ST_STRIDE;
        uint32_t dA = tb + OFF_AH + row * ROWB + half * 32;
        const char* sAh = (const char*)(g_ah + (long)node * KTOT + c * 32 + half * 16);
        const char* sAl = (const char*)(g_al + (long)node * KTOT + c * 32 + half * 16);
        CP16(dA,      sAh,      avalid);
        CP16(dA + 16, sAh + 16, avalid);
        CP16(dA + (OFF_AL - OFF_AH),      sAl,      avalid);
        CP16(dA + (OFF_AL - OFF_AH) + 16, sAl + 16, avalid);
        uint32_t dB = tb + OFF_BH + row * ROWB + half * 32;
        const char* sBh = (const char*)(g_wth + lwoff + (long)row * KTOT + c * 32 + half * 16);
        const char* sBl = (const char*)(g_wtl + lwoff + (long)row * KTOT + c * 32 + half * 16);
        CP16(dB,      sBh,      16u);
        CP16(dB + 16, sBh + 16, 16u);
        CP16(dB + (OFF_BL - OFF_BH),      sBl,      16u);
        CP16(dB + (OFF_BL - OFF_BH) + 16, sBl + 16, 16u);
    };

    int wm = (wid & 3) * 32;
    int wn = (wid >> 2) * 64;
    int l2 = lane & 3, l4 = lane >> 2;

    float acc[2][8][4];
    #pragma unroll
    for (int t = 0; t < 2; t++)
        #pragma unroll
        for (int j = 0; j < 8; j++)
            #pragma unroll
            for (int i = 0; i < 4; i++) acc[t][j][i] = 0.f;

    int arow0 = (lane & 7) + ((lane >> 3) & 1) * 8;
    int aseg  = (lane >> 4) * 16;
    int brow0 = (lane & 7) + (lane >> 4) * 8;
    int bseg  = ((lane >> 3) & 1) * 16;

    copy_chunk(0, 0);
    CP_COMMIT();

    for (int c = 0; c < NCHK; c++) {
        int st = c & 1;
        if (c + 1 < NCHK) {
            copy_chunk(c + 1, st ^ 1);
            CP_COMMIT();
            CP_WAIT(1);
        } else {
            CP_WAIT(0);
        }
        __syncthreads();
        uint32_t tb = sb + SM_TILES + st * ST_STRIDE;
        #pragma unroll
        for (int ks = 0; ks < 2; ks++) {
            int k0b = ks * 32;
            uint32_t ah[2][4], alr[2][4], bb[4][4];
            #pragma unroll
            for (int t = 0; t < 2; t++) {
                uint32_t ra = tb + OFF_AH + (uint32_t)(wm + t * 16 + arow0) * ROWB + k0b + aseg;
                ldsm_x4(ra, ah[t]);
                ldsm_x4(ra + (OFF_AL - OFF_AH), alr[t]);
            }
            #pragma unroll
            for (int p = 0; p < 4; p++) {
                uint32_t rb = tb + OFF_BH + (uint32_t)(wn + p * 16 + brow0) * ROWB + k0b + bseg;
                ldsm_x4(rb, bb[p]);
            }
            #pragma unroll
            for (int t = 0; t < 2; t++)
                #pragma unroll
                for (int p = 0; p < 4; p++) {
                    mma_bf16(acc[t][2 * p],     ah[t],  &bb[p][0]);
                    mma_bf16(acc[t][2 * p + 1], ah[t],  &bb[p][2]);
                }
            #pragma unroll
            for (int t = 0; t < 2; t++)
                #pragma unroll
                for (int p = 0; p < 4; p++) {
                    mma_bf16(acc[t][2 * p],     alr[t], &bb[p][0]);
                    mma_bf16(acc[t][2 * p + 1], alr[t], &bb[p][2]);
                }
            #pragma unroll
            for (int p = 0; p < 4; p++) {
                uint32_t rb = tb + OFF_BL + (uint32_t)(wn + p * 16 + brow0) * ROWB + k0b + bseg;
                ldsm_x4(rb, bb[p]);
            }
            #pragma unroll
            for (int t = 0; t < 2; t++)
                #pragma unroll
                for (int p = 0; p < 4; p++) {
                    mma_bf16(acc[t][2 * p],     ah[t], &bb[p][0]);
                    mma_bf16(acc[t][2 * p + 1], ah[t], &bb[p][2]);
                }
        }
        __syncthreads();
    }

    // ---- epilogue: bias + LN + relu + residual (+ bf16 x write for next layer) ----
    float* red = (float*)(smem + SM_RED);
    float s[4] = {0.f, 0.f, 0.f, 0.f}, q[4] = {0.f, 0.f, 0.f, 0.f};
    #pragma unroll
    for (int t = 0; t < 2; t++)
        #pragma unroll
        for (int j = 0; j < 8; j++) {
            int col = wn + j * 8 + l2 * 2;
            float b0 = smf[col], b1 = smf[col + 1];
            acc[t][j][0] += b0; acc[t][j][1] += b1;
            acc[t][j][2] += b0; acc[t][j][3] += b1;
            s[2 * t]     += acc[t][j][0] + acc[t][j][1];
            q[2 * t]     += acc[t][j][0] * acc[t][j][0] + acc[t][j][1] * acc[t][j][1];
            s[2 * t + 1] += acc[t][j][2] + acc[t][j][3];
            q[2 * t + 1] += acc[t][j][2] * acc[t][j][2] + acc[t][j][3] * acc[t][j][3];
        }
    #pragma unroll
    for (int i = 0; i < 4; i++) {
        s[i] += __shfl_xor_sync(0xffffffffu, s[i], 1);
        q[i] += __shfl_xor_sync(0xffffffffu, q[i], 1);
        s[i] += __shfl_xor_sync(0xffffffffu, s[i], 2);
        q[i] += __shfl_xor_sync(0xffffffffu, q[i], 2);
    }
    int nh = wid >> 2;
    if (l2 == 0) {
        #pragma unroll
        for (int i = 0; i < 4; i++) {
            int rw = wm + i * 8 + l4;
            red[rw * 4 + nh * 2 + 0] = s[i];
            red[rw * 4 + nh * 2 + 1] = q[i];
        }
    }
    __syncthreads();
    float mean[4], inv[4];
    #pragma unroll
    for (int i = 0; i < 4; i++) {
        int rw = wm + i * 8 + l4;
        float tot  = red[rw * 4 + 0] + red[rw * 4 + 2];
        float totq = red[rw * 4 + 1] + red[rw * 4 + 3];
        float mu = tot * (1.0f / 128.0f);
        float var = totq * (1.0f / 128.0f) - mu * mu;
        mean[i] = mu;
        inv[i] = rsqrtf(var + 1e-5f);
    }
    #pragma unroll
    for (int t = 0; t < 2; t++) {
        #pragma unroll
        for (int half2 = 0; half2 < 2; half2++) {
            int ri = 2 * t + half2;
            int nodeR = m0 + wm + ri * 8 + l4;
            if (nodeR >= NN) continue;
            float mu = mean[ri], iv = inv[ri];
            #pragma unroll
            for (int j = 0; j < 8; j++) {
                int col = wn + j * 8 + l2 * 2;
                float g0 = smf[128 + col], g1 = smf[128 + col + 1];
                float e0 = smf[256 + col], e1 = smf[256 + col + 1];
                float2 res = *(const float2*)(xcur + (long)nodeR * D + col);
                float v0 = acc[t][j][half2 * 2 + 0];
                float v1 = acc[t][j][half2 * 2 + 1];
                float o0 = fmaxf((v0 - mu) * iv * g0 + e0, 0.f) + res.x;
                float o1 = fmaxf((v1 - mu) * iv * g1 + e1, 0.f) + res.y;
                *(float2*)(xnext + (long)nodeR * D + col) = make_float2(o0, o1);
                // bf16 hi/lo of new x into A block 12 (own rows only)
                __nv_bfloat16 h0 = __float2bfloat16(o0), h1 = __float2bfloat16(o1);
                long aoff = (long)nodeR * KTOT + 12 * 128 + col;
                *(uint32_t*)(g_ah + aoff) = pkbf(h0, h1);
                *(uint32_t*)(g_al + aoff) = pkbf(
                    __float2bfloat16(o0 - __bfloat162float(h0)),
                    __float2bfloat16(o1 - __bfloat162float(h1)));
            }
        }
    }
}

// ---------------- final distmult scoring ----------------
__global__ __launch_bounds__(256) void k_score(
    const float* __restrict__ qw,
    const int* __restrict__ src,
    const int* __restrict__ rel,
    const int* __restrict__ dst,
    float* __restrict__ out)
{
    int gt = blockIdx.x * blockDim.x + threadIdx.x;
    int w = gt >> 5;
    int lane = gt & 31;
    if (w >= QB * QK) return;
    int s = src[w], r = rel[w], d = dst[w];
    int off = lane * 4;
    float4 a = *(const float4*)(g_xa + (long)s * D + off);
    float4 q = *(const float4*)(qw + (long)r * D + off);
    float4 b = *(const float4*)(g_xa + (long)d * D + off);
    float v = a.x * q.x * b.x + a.y * q.y * b.y + a.z * q.z * b.z + a.w * q.w * b.w;
    #pragma unroll
    for (int o = 16; o > 0; o >>= 1) v += __shfl_xor_sync(0xffffffffu, v, o);
    if (lane == 0) out[w] = v;
}

// ---------------- launch ----------------
extern "C" void kernel_launch(void* const* d_in, const int* in_sizes, int n_in,
                              void* d_out, int out_size) {
    const float* x0    = (const float*)d_in[0];
    const int*   eidx  = (const int*)  d_in[1];
    const int*   etype = (const int*)  d_in[2];
    const float* ew    = (const float*)d_in[3];
    const float* relw  = (const float*)d_in[4];
    const float* linw  = (const float*)d_in[5];
    const float* linb  = (const float*)d_in[6];
    const float* lng   = (const float*)d_in[7];
    const float* lnb   = (const float*)d_in[8];
    const float* qw    = (const float*)d_in[9];
    const int*   src   = (const int*)  d_in[10];
    const int*   rel   = (const int*)  d_in[11];
    const int*   dst   = (const int*)  d_in[12];
    float* out = (float*)d_out;

    const int* esrc = eidx;
    const int* edst = eidx + NE;

    static int smem_set = 0;
    if (!smem_set) {
        cudaFuncSetAttribute(k_gemm, cudaFuncAttributeMaxDynamicSharedMemorySize, GEMM_SMEM);
        smem_set = 1;
    }

    k_init<<<(NN + 255) / 256, 256>>>();
    k_hist<<<(NE + 255) / 256, 256>>>(edst);
    k_scan<<<1, 1024>>>();
    k_scatter<<<(NE + 255) / 256, 256>>>(esrc, edst, etype, ew);
    k_logsum<<<(NN + 255) / 256, 256>>>();
    k_scales<<<(NN + 255) / 256, 256>>>();
    k_copy<<<(NN * 32 + 255) / 256, 256>>>(x0);
    k_wsplit<<<((long)NL * D * KTOT + 255) / 256, 256>>>(linw);

    for (int l = 0; l < NL; l++) {
        int parity = l & 1;
        k_agg<<<(NN * 32 + 255) / 256, 256>>>(parity, x0, relw + (long)l * NREL * D);
        k_gemm<<<(NN + 127) / 128, 256, GEMM_SMEM>>>(parity, (long)l * D * KTOT,
                                                     linb + (long)l * D, lng + (long)l * D,
                                                     lnb + (long)l * D);
    }

    k_score<<<(QB * QK * 32 + 255) / 256, 256>>>(qw, src, rel, dst, out);
}